// round 1
// baseline (speedup 1.0000x reference)
#include <cuda_runtime.h>
#include <cuda_bf16.h>

// out[bt, i*16 + j] = x[bt, i] * W[i, j] + b[i, j]
// B*T = 32768, C_IN = 128, C_OUT = 16 -> out has 67,108,864 floats (256 MB).
// Pure HBM-store-bound. One thread per float4 of output, persistent grid.

#define C_IN   128
#define C_OUT  16
#define NBT    (64 * 512)
#define WB_F4  (C_IN * C_OUT / 4)               // 512 float4 for W (and for b)
#define TOTAL_F4 ((unsigned)NBT * C_IN * C_OUT / 4)  // 16,777,216

__global__ __launch_bounds__(256, 8)
void real_embedding_kernel(const float* __restrict__ x,
                           const float* __restrict__ W,
                           const float* __restrict__ b,
                           float4* __restrict__ out,
                           unsigned total_f4)
{
    __shared__ float4 sW[WB_F4];
    __shared__ float4 sB[WB_F4];

    const unsigned t = threadIdx.x;
    // Stage W and b (2048 floats each = 512 float4 each) into shared.
    const float4* W4 = (const float4*)W;
    const float4* B4 = (const float4*)b;
    sW[t]       = W4[t];
    sW[t + 256] = W4[t + 256];
    sB[t]       = B4[t];
    sB[t + 256] = B4[t + 256];
    __syncthreads();

    const unsigned stride = gridDim.x * blockDim.x;
    for (unsigned gid = blockIdx.x * blockDim.x + t; gid < total_f4; gid += stride) {
        // gid -> (bt, i, quad): out float4 layout is [bt][i][q] with q in 0..3
        const unsigned q  = gid & 3u;
        const unsigned i  = (gid >> 2) & 127u;
        const unsigned bt = gid >> 9;

        const float xv = __ldg(&x[bt * C_IN + i]);

        const float4 w  = sW[i * 4 + q];
        const float4 bb = sB[i * 4 + q];

        float4 o;
        o.x = fmaf(xv, w.x, bb.x);
        o.y = fmaf(xv, w.y, bb.y);
        o.z = fmaf(xv, w.z, bb.z);
        o.w = fmaf(xv, w.w, bb.w);
        out[gid] = o;
    }
}

extern "C" void kernel_launch(void* const* d_in, const int* in_sizes, int n_in,
                              void* d_out, int out_size) {
    const float* x = (const float*)d_in[0];
    const float* W = (const float*)d_in[1];
    const float* b = (const float*)d_in[2];
    float4* out = (float4*)d_out;

    (void)in_sizes; (void)n_in; (void)out_size;

    // Persistent-style grid: 148 SMs * 8 blocks of 256 threads.
    const int blocks = 148 * 8;
    real_embedding_kernel<<<blocks, 256>>>(x, W, b, out, TOTAL_F4);
}

// round 2
// speedup vs baseline: 1.0199x; 1.0199x over previous
#include <cuda_runtime.h>
#include <cuda_bf16.h>

// out[bt, i*16 + j] = x[bt, i] * W[i, j] + b[i, j]
// B*T = 32768, C_IN = 128, C_OUT = 16 -> 67,108,864 floats out (256 MB). HBM-store-bound.
//
// Each thread owns a fixed (i, h) pair (h = which 8-float half of the 16 outputs
// for feature i) because the grid stride is a multiple of 256 float8s per bt row.
// W/b slices are loaded to registers ONCE; the hot loop is LDG x -> 8 FFMA -> STG.256.

#define C_IN   128
#define C_OUT  16
#define NBT    (64 * 512)
#define TOTAL_F8 ((unsigned)NBT * C_IN * C_OUT / 8)   // 8,388,608

__global__ __launch_bounds__(256, 8)
void real_embedding_kernel(const float* __restrict__ x,
                           const float* __restrict__ W,
                           const float* __restrict__ b,
                           float* __restrict__ out,
                           unsigned total_f8)
{
    const unsigned tid0   = blockIdx.x * blockDim.x + threadIdx.x;
    const unsigned stride = gridDim.x * blockDim.x;   // multiple of 256

    // Decode the per-thread constant (i, h): gid & 255 is invariant across the loop.
    const unsigned h = tid0 & 1u;            // which half (8 outputs) of the 16
    const unsigned i = (tid0 >> 1) & 127u;   // input feature

    // Hoist this thread's W/b slice into registers (one-time, coalesced).
    const float4* W4 = (const float4*)(W + i * C_OUT + h * 8);
    const float4* B4 = (const float4*)(b + i * C_OUT + h * 8);
    const float4 w0 = W4[0], w1 = W4[1];
    const float4 c0 = B4[0], c1 = B4[1];

    const unsigned bt_step = stride >> 8;    // bt advance per iteration
    unsigned bt = tid0 >> 8;

    for (unsigned gid = tid0; gid < total_f8; gid += stride, bt += bt_step) {
        const float xv = __ldg(x + (size_t)bt * C_IN + i);

        const float o0 = fmaf(xv, w0.x, c0.x);
        const float o1 = fmaf(xv, w0.y, c0.y);
        const float o2 = fmaf(xv, w0.z, c0.z);
        const float o3 = fmaf(xv, w0.w, c0.w);
        const float o4 = fmaf(xv, w1.x, c1.x);
        const float o5 = fmaf(xv, w1.y, c1.y);
        const float o6 = fmaf(xv, w1.z, c1.z);
        const float o7 = fmaf(xv, w1.w, c1.w);

        float* dst = out + (size_t)gid * 8;  // 32B-aligned
        asm volatile(
            "st.global.v8.f32 [%0], {%1, %2, %3, %4, %5, %6, %7, %8};"
            :: "l"(dst),
               "f"(o0), "f"(o1), "f"(o2), "f"(o3),
               "f"(o4), "f"(o5), "f"(o6), "f"(o7)
            : "memory");
    }
}

extern "C" void kernel_launch(void* const* d_in, const int* in_sizes, int n_in,
                              void* d_out, int out_size) {
    const float* x = (const float*)d_in[0];
    const float* W = (const float*)d_in[1];
    const float* b = (const float*)d_in[2];
    float* out = (float*)d_out;

    (void)in_sizes; (void)n_in; (void)out_size;

    // Persistent-style grid: 148 SMs * 8 blocks of 256 threads; stride = 303,104
    // (multiple of 256 -> per-thread (i, h) invariant).
    const int blocks = 148 * 8;
    real_embedding_kernel<<<blocks, 256>>>(x, W, b, out, TOTAL_F8);
}

// round 3
// speedup vs baseline: 1.0375x; 1.0173x over previous
#include <cuda_runtime.h>
#include <cuda_bf16.h>

// out[bt, i*16 + j] = x[bt, i] * W[i, j] + b[i, j]
// B*T = 32768, C_IN = 128, C_OUT = 16 -> 256 MB out. HBM-store-bound.
//
// R2 finding: kernel is limited by the L2->DRAM writeback path, not SM-side work.
// This round: identical structure to R2 but stores use .cs (evict-first streaming)
// so dirty output lines are written back eagerly instead of via capacity eviction.

#define C_IN   128
#define C_OUT  16
#define NBT    (64 * 512)
#define TOTAL_F8 ((unsigned)NBT * C_IN * C_OUT / 8)   // 8,388,608

__global__ __launch_bounds__(256, 8)
void real_embedding_kernel(const float* __restrict__ x,
                           const float* __restrict__ W,
                           const float* __restrict__ b,
                           float* __restrict__ out,
                           unsigned total_f8)
{
    const unsigned tid0   = blockIdx.x * blockDim.x + threadIdx.x;
    const unsigned stride = gridDim.x * blockDim.x;   // multiple of 256

    // Per-thread constant (i, h): gid & 255 is invariant across the loop.
    const unsigned h = tid0 & 1u;            // which half (8 outputs) of the 16
    const unsigned i = (tid0 >> 1) & 127u;   // input feature

    // Hoist this thread's W/b slice into registers (one-time, coalesced).
    const float4* W4 = (const float4*)(W + i * C_OUT + h * 8);
    const float4* B4 = (const float4*)(b + i * C_OUT + h * 8);
    const float4 w0 = W4[0], w1 = W4[1];
    const float4 c0 = B4[0], c1 = B4[1];

    const unsigned bt_step = stride >> 8;    // bt advance per iteration
    unsigned bt = tid0 >> 8;

    for (unsigned gid = tid0; gid < total_f8; gid += stride, bt += bt_step) {
        const float xv = __ldg(x + (size_t)bt * C_IN + i);

        const float o0 = fmaf(xv, w0.x, c0.x);
        const float o1 = fmaf(xv, w0.y, c0.y);
        const float o2 = fmaf(xv, w0.z, c0.z);
        const float o3 = fmaf(xv, w0.w, c0.w);
        const float o4 = fmaf(xv, w1.x, c1.x);
        const float o5 = fmaf(xv, w1.y, c1.y);
        const float o6 = fmaf(xv, w1.z, c1.z);
        const float o7 = fmaf(xv, w1.w, c1.w);

        float* dst = out + (size_t)gid * 8;  // 32B-aligned
        // Streaming (evict-first) 256-bit store: output lines are dead after
        // write, so don't let them linger dirty in L2.
        asm volatile(
            "st.global.cs.v8.f32 [%0], {%1, %2, %3, %4, %5, %6, %7, %8};"
            :: "l"(dst),
               "f"(o0), "f"(o1), "f"(o2), "f"(o3),
               "f"(o4), "f"(o5), "f"(o6), "f"(o7)
            : "memory");
    }
}

extern "C" void kernel_launch(void* const* d_in, const int* in_sizes, int n_in,
                              void* d_out, int out_size) {
    const float* x = (const float*)d_in[0];
    const float* W = (const float*)d_in[1];
    const float* b = (const float*)d_in[2];
    float* out = (float*)d_out;

    (void)in_sizes; (void)n_in; (void)out_size;

    const int blocks = 148 * 8;   // persistent grid, stride multiple of 256
    real_embedding_kernel<<<blocks, 256>>>(x, W, b, out, TOTAL_F8);
}

// round 4
// speedup vs baseline: 1.0406x; 1.0030x over previous
#include <cuda_runtime.h>
#include <cuda_bf16.h>
#include <cstdint>

// out[bt, i*16 + j] = x[bt, i] * W[i, j] + b[i, j]
// 256 MB output, pure write-stream. R1-R3 showed per-thread STG paths all cap at
// ~4.5 TB/s with DRAM 44% idle -> suspect SM store-issue path. This round the
// stores go through bulk TMA: compute a 16KB chunk (2 bt rows) into SMEM,
// cp.async.bulk it to GMEM. Double buffered.

#define C_IN   128
#define C_OUT  16
#define NBT    (64 * 512)
#define CHUNK_FLOATS 4096               // 2 bt rows of 2048 floats
#define CHUNK_BYTES  (CHUNK_FLOATS * 4) // 16384
#define NCHUNKS      ((unsigned)NBT * C_IN * C_OUT / CHUNK_FLOATS)  // 16384

__device__ __forceinline__ uint32_t smem_u32(const void* p) {
    uint32_t a;
    asm("{ .reg .u64 t; cvta.to.shared.u64 t, %1; cvt.u32.u64 %0, t; }"
        : "=r"(a) : "l"(p));
    return a;
}

__global__ __launch_bounds__(256)
void real_embedding_tma_kernel(const float* __restrict__ x,
                               const float* __restrict__ W,
                               const float* __restrict__ b,
                               float* __restrict__ out)
{
    __shared__ __align__(128) float buf[2][CHUNK_FLOATS];

    const unsigned t  = threadIdx.x;
    const unsigned j0 = (t & 3u) * 4u;     // output sub-column, loop-invariant
    const unsigned i0 = t >> 2;            // feature for even k  (0..63)
    const unsigned i1 = i0 + 64;           // feature for odd k

    // Per-thread W/b slices in registers (loop-invariant).
    const float4 wa = *(const float4*)(W + i0 * C_OUT + j0);
    const float4 wb = *(const float4*)(W + i1 * C_OUT + j0);
    const float4 ca = *(const float4*)(b + i0 * C_OUT + j0);
    const float4 cb = *(const float4*)(b + i1 * C_OUT + j0);

    unsigned iter = 0;
    for (unsigned c = blockIdx.x; c < NCHUNKS; c += gridDim.x, iter++) {
        const unsigned p = iter & 1u;

        // Make sure the TMA that last read buffer p has finished reading it.
        if (t == 0 && iter >= 2) {
            asm volatile("cp.async.bulk.wait_group.read 1;" ::: "memory");
        }
        __syncthreads();

        // Chunk c covers output floats [c*4096, (c+1)*4096) = bt rows {2c, 2c+1}.
        const unsigned bt0 = c * 2u;
        const float x00 = __ldg(x + (size_t)bt0 * C_IN + i0);
        const float x01 = __ldg(x + (size_t)bt0 * C_IN + i1);
        const float x10 = __ldg(x + (size_t)(bt0 + 1) * C_IN + i0);
        const float x11 = __ldg(x + (size_t)(bt0 + 1) * C_IN + i1);

        float4 o;
        // k=0: bt0, i0   -> smem offset 0*1024 + t*4
        o.x = fmaf(x00, wa.x, ca.x); o.y = fmaf(x00, wa.y, ca.y);
        o.z = fmaf(x00, wa.z, ca.z); o.w = fmaf(x00, wa.w, ca.w);
        *(float4*)&buf[p][t * 4] = o;
        // k=1: bt0, i1
        o.x = fmaf(x01, wb.x, cb.x); o.y = fmaf(x01, wb.y, cb.y);
        o.z = fmaf(x01, wb.z, cb.z); o.w = fmaf(x01, wb.w, cb.w);
        *(float4*)&buf[p][1024 + t * 4] = o;
        // k=2: bt0+1, i0
        o.x = fmaf(x10, wa.x, ca.x); o.y = fmaf(x10, wa.y, ca.y);
        o.z = fmaf(x10, wa.z, ca.z); o.w = fmaf(x10, wa.w, ca.w);
        *(float4*)&buf[p][2048 + t * 4] = o;
        // k=3: bt0+1, i1
        o.x = fmaf(x11, wb.x, cb.x); o.y = fmaf(x11, wb.y, cb.y);
        o.z = fmaf(x11, wb.z, cb.z); o.w = fmaf(x11, wb.w, cb.w);
        *(float4*)&buf[p][3072 + t * 4] = o;

        __syncthreads();

        if (t == 0) {
            asm volatile("fence.proxy.async.shared::cta;" ::: "memory");
            const uint32_t src = smem_u32(&buf[p][0]);
            float* dst = out + (size_t)c * CHUNK_FLOATS;
            asm volatile(
                "cp.async.bulk.global.shared::cta.bulk_group [%0], [%1], %2;"
                :: "l"(dst), "r"(src), "n"(CHUNK_BYTES) : "memory");
            asm volatile("cp.async.bulk.commit_group;" ::: "memory");
        }
    }

    // Drain all outstanding bulk stores before grid exit.
    if (t == 0) {
        asm volatile("cp.async.bulk.wait_group 0;" ::: "memory");
    }
}

extern "C" void kernel_launch(void* const* d_in, const int* in_sizes, int n_in,
                              void* d_out, int out_size) {
    const float* x = (const float*)d_in[0];
    const float* W = (const float*)d_in[1];
    const float* b = (const float*)d_in[2];
    float* out = (float*)d_out;

    (void)in_sizes; (void)n_in; (void)out_size;

    // 32KB static smem/block -> 7 blocks/SM; 148 SMs.
    const int blocks = 148 * 7;
    real_embedding_tma_kernel<<<blocks, 256>>>(x, W, b, out);
}